// round 16
// baseline (speedup 1.0000x reference)
#include <cuda_runtime.h>
#include <cuda_fp16.h>
#include <cstdint>
#include <cstddef>

#define NNODES 20000
#define HID    512
#define NEDGE  160000
#define NTYPES 5
#define NET    6
#define FIN    64
#define NWMAT  12
#define TOFF   ((size_t)NNODES * HID)
#define LOSCALE 1024.f

// ---------------- scratch (__device__ globals; no allocs allowed) -------------
__device__ float g_h  [NTYPES * NNODES * HID];
__device__ float g_h2 [NTYPES * NNODES * HID];
__device__ float g_y1 [NNODES * HID];
__device__ float g_y4 [NNODES * HID];
__device__ half g_Ahi[NET * NNODES * HID];
__device__ half g_Alo[NET * NNODES * HID];
__device__ half g_Mhi[NET * NNODES * HID];
__device__ half g_Mlo[NET * NNODES * HID];
__device__ half g_xhi[NTYPES * NNODES * FIN];
__device__ half g_xlo[NTYPES * NNODES * FIN];
__device__ half g_Winhi[NTYPES * HID * FIN];
__device__ half g_Winlo[NTYPES * HID * FIN];
__device__ half g_W1hi[NWMAT * HID * HID];
__device__ half g_W1lo[NWMAT * HID * HID];
__device__ half g_W2hi[NWMAT * HID * HID];
__device__ half g_W2lo[NWMAT * HID * HID];
// CSR scratch
__device__ int g_cnt [NET * NNODES];
__device__ int g_off [NET * (NNODES + 1)];
__device__ int g_curp[NET * NNODES];
__device__ int g_eidx[NET * NEDGE];

// EDGE_TYPES = ((4,1),(1,0),(0,2),(2,3),(3,0),(1,4))
__constant__ int c_ES[NET] = {4, 1, 0, 2, 3, 1};
__constant__ int c_ED[NET] = {1, 0, 2, 3, 0, 4};
// Dead-cone-pruned active type lists:
//  [0..5] identity; [6..9] layer 0: {0,1,3,4}; [10..11] layer 1: {1,4}
__constant__ int c_TLA[12] = {0, 1, 2, 3, 4, 5,  0, 1, 3, 4,  1, 4};
#define TL_ID 0
#define TL_L0 6
#define TL_L1 10
__constant__ int c_WMAP[6] = {0, 1, 3, 4, 7, 10};   // live (l*NET+t) weight mats
__constant__ int c_CSRT[4] = {0, 1, 3, 4};          // edge types ever gathered

// ---------------- family-common PTX helpers (sm_80+) --------------------------
__device__ __forceinline__ uint32_t smem_u32(const void* p) {
    uint32_t a;
    asm("{ .reg .u64 t; cvta.to.shared.u64 t, %1; cvt.u32.u64 %0, t; }" : "=r"(a) : "l"(p));
    return a;
}
__device__ __forceinline__ void cpasync16(uint32_t s, const void* g, int sz) {
    asm volatile("cp.async.cg.shared.global [%0], [%1], 16, %2;" :: "r"(s), "l"(g), "r"(sz));
}
__device__ __forceinline__ void cp_commit() { asm volatile("cp.async.commit_group;"); }
template<int N>
__device__ __forceinline__ void cp_wait() { asm volatile("cp.async.wait_group %0;" :: "n"(N)); }

__device__ __forceinline__ void ldsm4(uint32_t* r, uint32_t a) {
    asm volatile("ldmatrix.sync.aligned.m8n8.x4.shared.b16 {%0,%1,%2,%3}, [%4];"
                 : "=r"(r[0]), "=r"(r[1]), "=r"(r[2]), "=r"(r[3]) : "r"(a));
}
__device__ __forceinline__ void ldsm2(uint32_t* r, uint32_t a) {
    asm volatile("ldmatrix.sync.aligned.m8n8.x2.shared.b16 {%0,%1}, [%2];"
                 : "=r"(r[0]), "=r"(r[1]) : "r"(a));
}
// fp16 data, fp32 accumulate (same 16 cyc/SMSP issue rate as bf16 — measured R14)
__device__ __forceinline__ void mma16816(float* d, const uint32_t* a, const uint32_t* b) {
    asm volatile("mma.sync.aligned.m16n8k16.row.col.f32.f16.f16.f32 "
                 "{%0,%1,%2,%3}, {%4,%5,%6,%7}, {%8,%9}, {%0,%1,%2,%3};"
                 : "+f"(d[0]), "+f"(d[1]), "+f"(d[2]), "+f"(d[3])
                 : "r"(a[0]), "r"(a[1]), "r"(a[2]), "r"(a[3]), "r"(b[0]), "r"(b[1]));
}
// fp16 split: v = hi + lo/LOSCALE (lo pre-scaled by 1024 to stay normal-range)
__device__ __forceinline__ void h16_split2(float v0, float v1, uint32_t& hp, uint32_t& lp) {
    half h0 = __float2half_rn(v0), h1 = __float2half_rn(v1);
    half q0 = __float2half_rn((v0 - __half2float(h0)) * LOSCALE);
    half q1 = __float2half_rn((v1 - __half2float(h1)) * LOSCALE);
    hp = ((uint32_t)__half_as_ushort(h1) << 16) | __half_as_ushort(h0);
    lp = ((uint32_t)__half_as_ushort(q1) << 16) | __half_as_ushort(q0);
}

// ---------------------------------------------------------------------
// Batched 3-product split-fp16 GEMM on mma.sync; t = c_TLA[tlbase + blockIdx.z].
// 2-stage cp.async + OCCUPANCY 2 (smem 80KB/CTA, 128-reg cap) — R15-proven.
// acc = Ah*Wh + (Ah*Wl + Al*Wh)/1024, all fp32 accumulate.
// MODE 0: GEMM1  -> relu, fp16 hi/lo out to Chi/Clo + t*TOFF
// MODE 1: GEMM2  -> t==1 raw->y1, t==4 raw->y4, else relu -> C + ED[t]*TOFF
// MODE 2: inproj -> relu -> fp32 C + t*TOFF
// CTA 128x128, BK=32, 8 warps.
// ---------------------------------------------------------------------
#define MS_A_HI 0
#define MS_A_LO 10240
#define MS_B_HI 20480
#define MS_B_LO 30720
#define MS_STAGE 40960
#define MS_TOTAL (2 * MS_STAGE)

template<int MODE, int LDK>
__global__ __launch_bounds__(256, 2)
void gemm_mma_b(const half* __restrict__ Ahi, const half* __restrict__ Alo,
                size_t aStride, int tlbase,
                const half* __restrict__ Whi, const half* __restrict__ Wlo,
                const float* __restrict__ bias,
                float* __restrict__ C,
                half* __restrict__ Chi, half* __restrict__ Clo,
                float* __restrict__ y1, float* __restrict__ y4,
                int M)
{
    constexpr int NKT = LDK / 32;
    extern __shared__ char smem[];
    const uint32_t sb = smem_u32(smem);
    const int t    = c_TLA[tlbase + blockIdx.z];
    const int tid  = threadIdx.x;
    const int lane = tid & 31;
    const int wid  = tid >> 5;
    const int wm   = (wid >> 2) * 64;
    const int wn   = (wid & 3) * 32;
    const int bm   = blockIdx.x * 128;
    const int bn   = blockIdx.y * 128;

    Ahi += (size_t)t * aStride;
    Alo += (size_t)t * aStride;
    Whi += (size_t)t * (size_t)HID * LDK;
    Wlo += (size_t)t * (size_t)HID * LDK;
    bias += (size_t)t * HID;

    auto load_stage = [&](int st, int kt) {
        const int kc = kt * 32;
        const uint32_t sbase = sb + st * MS_STAGE;
#pragma unroll
        for (int j = 0; j < 2; ++j) {
            const int c   = tid + j * 256;
            const int row = c >> 2;
            const int c16 = c & 3;
            const uint32_t so = (uint32_t)(row * 80 + c16 * 16);
            const int gr = bm + row;
            const int sz = (gr < M) ? 16 : 0;
            const size_t ga = (size_t)gr * LDK + kc + c16 * 8;
            cpasync16(sbase + MS_A_HI + so, Ahi + ga, sz);
            cpasync16(sbase + MS_A_LO + so, Alo + ga, sz);
            const size_t gb = (size_t)(bn + row) * LDK + kc + c16 * 8;
            cpasync16(sbase + MS_B_HI + so, Whi + gb, 16);
            cpasync16(sbase + MS_B_LO + so, Wlo + gb, 16);
        }
        cp_commit();
    };

    float acc[4][4][4];
    float accX[4][4][4];
#pragma unroll
    for (int mi = 0; mi < 4; ++mi)
#pragma unroll
        for (int ni = 0; ni < 4; ++ni)
#pragma unroll
            for (int q = 0; q < 4; ++q) { acc[mi][ni][q] = 0.f; }

    load_stage(0, 0);

    const uint32_t a_row = (uint32_t)(lane & 15);
    const uint32_t a_k16 = (uint32_t)((lane >> 4) * 16);
    const uint32_t b_row = (uint32_t)(lane & 7);
    const uint32_t b_k16 = (uint32_t)(((lane >> 3) & 1) * 16);

#pragma unroll 1
    for (int kt = 0; kt < NKT; ++kt) {
        if (kt + 1 < NKT) { load_stage((kt + 1) & 1, kt + 1); cp_wait<1>(); }
        else              { cp_wait<0>(); }
        __syncthreads();

        const uint32_t sbase = sb + (uint32_t)(kt & 1) * MS_STAGE;
#pragma unroll
        for (int k2 = 0; k2 < 2; ++k2) {
            const uint32_t koff = (uint32_t)(k2 * 32);
            uint32_t ah[4][4], al[4][4], bh[4][2], bl[4][2];
#pragma unroll
            for (int mi = 0; mi < 4; ++mi) {
                uint32_t ad = sbase + (uint32_t)((wm + mi * 16 + a_row) * 80) + a_k16 + koff;
                ldsm4(ah[mi], ad + MS_A_HI);
                ldsm4(al[mi], ad + MS_A_LO);
            }
#pragma unroll
            for (int ni = 0; ni < 4; ++ni) {
                uint32_t bd = sbase + (uint32_t)((wn + ni * 8 + b_row) * 80) + b_k16 + koff;
                ldsm2(bh[ni], bd + MS_B_HI);
                ldsm2(bl[ni], bd + MS_B_LO);
            }
            // cross terms accumulate into the SAME fp32 accumulator; lo planes
            // are pre-scaled by 1024, folded out once in the epilogue via accX
            // trick: accumulate hi*hi into acc, cross into acc as well but the
            // cross contributions are 1024x too big -> keep them separate is
            // not possible within 128 regs; instead scale at split time:
            // lo stored pre-DIVIDED? No: we store lo*1024 and divide the cross
            // product sum by 1024 — achieved by accumulating cross terms into
            // acc AFTER multiplying A-lo/W-lo fragments... HW can't. Solution:
            // store lo planes NOT pre-scaled (raw residual, subnormal-safe for
            // fp16? residual of values O(100) is O(0.02) -> normal range).
            // So: plain acc += Ah*Wh + Ah*Wl + Al*Wh, all same scale.
            (void)accX;
#pragma unroll
            for (int mi = 0; mi < 4; ++mi)
#pragma unroll
                for (int ni = 0; ni < 4; ++ni) {
                    mma16816(acc[mi][ni], ah[mi], bh[ni]);
                    mma16816(acc[mi][ni], ah[mi], bl[ni]);
                    mma16816(acc[mi][ni], al[mi], bh[ni]);
                }
        }
        __syncthreads();
    }

    // ---- per-mode output routing ----
    float* Cout = nullptr;
    bool doRelu = true;
    if (MODE == 0) {
        Chi += (size_t)t * TOFF;
        Clo += (size_t)t * TOFF;
    } else if (MODE == 1) {
        const int d = c_ED[t];
        if (t == 1)      { Cout = y1; doRelu = false; }
        else if (t == 4) { Cout = y4; doRelu = false; }
        else             { Cout = C + (size_t)d * TOFF; }
    } else {
        Cout = C + (size_t)t * TOFF;
    }

#pragma unroll
    for (int mi = 0; mi < 4; ++mi) {
        const int r0 = bm + wm + mi * 16 + (lane >> 2);
#pragma unroll
        for (int half2i = 0; half2i < 2; ++half2i) {
            const int r = r0 + half2i * 8;
            if (r >= M) continue;
#pragma unroll
            for (int ni = 0; ni < 4; ++ni) {
                const int c = wn + ni * 8 + (lane & 3) * 2 + bn;
                float v0 = acc[mi][ni][half2i * 2 + 0] + bias[c];
                float v1 = acc[mi][ni][half2i * 2 + 1] + bias[c + 1];
                if (MODE == 0) {
                    v0 = fmaxf(v0, 0.f); v1 = fmaxf(v1, 0.f);
                    // raw-residual split (lo not pre-scaled; residuals of
                    // O(100) values are O(0.02) -> fp16 normal range)
                    half h0 = __float2half_rn(v0), h1 = __float2half_rn(v1);
                    half q0 = __float2half_rn(v0 - __half2float(h0));
                    half q1 = __float2half_rn(v1 - __half2float(h1));
                    uint32_t hp = ((uint32_t)__half_as_ushort(h1) << 16) | __half_as_ushort(h0);
                    uint32_t lp = ((uint32_t)__half_as_ushort(q1) << 16) | __half_as_ushort(q0);
                    *(uint32_t*)(Chi + (size_t)r * HID + c) = hp;
                    *(uint32_t*)(Clo + (size_t)r * HID + c) = lp;
                } else {
                    if (doRelu) { v0 = fmaxf(v0, 0.f); v1 = fmaxf(v1, 0.f); }
                    *(float2*)(Cout + (size_t)r * HID + c) = make_float2(v0, v1);
                }
            }
        }
    }
}

// ---------------------------------------------------------------------
// CSR build for ACTIVE edge types only: histogram -> scan -> fill
// ---------------------------------------------------------------------
__global__ void hist_kernel(const int* __restrict__ edges, int* __restrict__ cnt)
{
    const int i = blockIdx.x * blockDim.x + threadIdx.x;
    if (i >= 4 * NEDGE) return;
    const int t = c_CSRT[i / NEDGE], e = i % NEDGE;
    const int d = edges[(size_t)t * 2 * NEDGE + NEDGE + e];
    atomicAdd(&cnt[t * NNODES + d], 1);
}

__global__ void scan_kernel(const int* __restrict__ cnt, int* __restrict__ off,
                            int* __restrict__ curp)
{
    const int t = c_CSRT[blockIdx.x];
    const int tid = threadIdx.x;
    const int lane = tid & 31, wid = tid >> 5;
    __shared__ int wsum[32];
    __shared__ int chunkTotal;
    int carry = 0;
    for (int base = 0; base < NNODES; base += 1024) {
        const int idx = base + tid;
        int v = (idx < NNODES) ? cnt[t * NNODES + idx] : 0;
        int x = v;
#pragma unroll
        for (int o = 1; o < 32; o <<= 1) {
            int y = __shfl_up_sync(0xffffffffu, x, o);
            if (lane >= o) x += y;
        }
        if (lane == 31) wsum[wid] = x;
        __syncthreads();
        if (wid == 0) {
            int w = wsum[lane];
#pragma unroll
            for (int o = 1; o < 32; o <<= 1) {
                int y = __shfl_up_sync(0xffffffffu, w, o);
                if (lane >= o) w += y;
            }
            wsum[lane] = w;
            if (lane == 31) chunkTotal = w;
        }
        __syncthreads();
        const int incl = x + (wid > 0 ? wsum[wid - 1] : 0);
        const int excl = carry + incl - v;
        if (idx < NNODES) {
            off[t * (NNODES + 1) + idx] = excl;
            curp[t * NNODES + idx] = excl;
        }
        carry += chunkTotal;
        __syncthreads();
    }
    if (tid == 0) off[t * (NNODES + 1) + NNODES] = carry;
}

__global__ void fill_kernel(const int* __restrict__ edges, int* __restrict__ curp,
                            int* __restrict__ eidx)
{
    const int i = blockIdx.x * blockDim.x + threadIdx.x;
    if (i >= 4 * NEDGE) return;
    const int t = c_CSRT[i / NEDGE], e = i % NEDGE;
    const int s = edges[(size_t)t * 2 * NEDGE + e];
    const int d = edges[(size_t)t * 2 * NEDGE + NEDGE + e];
    const int p = atomicAdd(&curp[t * NNODES + d], 1);
    eidx[t * NEDGE + p] = s;
}

// ---------------------------------------------------------------------
// Fused GIN aggregation via CSR gather + fp16 hi/lo split (proven 128-thr form;
// L2-bandwidth-bound at its floor).
// Layer 1 (useY): dst-0 self term computed inline as relu(y1[d] + y4[d]).
// ---------------------------------------------------------------------
__global__ __launch_bounds__(128)
void gather_split_kernel(const float* __restrict__ hcur, int tlbase, int useY,
                         const float* __restrict__ y1, const float* __restrict__ y4,
                         const int* __restrict__ off, const int* __restrict__ eidx,
                         half* __restrict__ Ahi, half* __restrict__ Alo)
{
    const int d = blockIdx.x;
    const int t = c_TLA[tlbase + blockIdx.y];
    const int c4 = threadIdx.x * 4;
    const int o0 = off[t * (NNODES + 1) + d];
    const int o1 = off[t * (NNODES + 1) + d + 1];
    const float* hsrc = hcur + (size_t)c_ES[t] * TOFF;
    const int* ei = eidx + (size_t)t * NEDGE;

    float4 acc;
    if (useY) {
        const float4 a = *(const float4*)(y1 + (size_t)d * HID + c4);
        const float4 b = *(const float4*)(y4 + (size_t)d * HID + c4);
        acc.x = fmaxf(a.x + b.x, 0.f);
        acc.y = fmaxf(a.y + b.y, 0.f);
        acc.z = fmaxf(a.z + b.z, 0.f);
        acc.w = fmaxf(a.w + b.w, 0.f);
    } else {
        acc = *(const float4*)(hcur + (size_t)c_ED[t] * TOFF + (size_t)d * HID + c4);
    }
#pragma unroll 4
    for (int e = o0; e < o1; ++e) {
        const int s = __ldg(&ei[e]);
        const float4 v = *(const float4*)(hsrc + (size_t)s * HID + c4);
        acc.x += v.x; acc.y += v.y; acc.z += v.z; acc.w += v.w;
    }
    // raw-residual fp16 split
    half h0 = __float2half_rn(acc.x), h1 = __float2half_rn(acc.y);
    half h2 = __float2half_rn(acc.z), h3 = __float2half_rn(acc.w);
    half l0 = __float2half_rn(acc.x - __half2float(h0));
    half l1 = __float2half_rn(acc.y - __half2float(h1));
    half l2 = __float2half_rn(acc.z - __half2float(h2));
    half l3 = __float2half_rn(acc.w - __half2float(h3));
    uint2 hv, lv;
    hv.x = ((uint32_t)__half_as_ushort(h1) << 16) | __half_as_ushort(h0);
    hv.y = ((uint32_t)__half_as_ushort(h3) << 16) | __half_as_ushort(h2);
    lv.x = ((uint32_t)__half_as_ushort(l1) << 16) | __half_as_ushort(l0);
    lv.y = ((uint32_t)__half_as_ushort(l3) << 16) | __half_as_ushort(l2);
    *(uint2*)(Ahi + (size_t)t * TOFF + (size_t)d * HID + c4) = hv;
    *(uint2*)(Alo + (size_t)t * TOFF + (size_t)d * HID + c4) = lv;
}

// ---------------------------------------------------------------------
__global__ void split_kernel(const float* __restrict__ a,
                             half* __restrict__ hi, half* __restrict__ lo, int n4)
{
    int i = blockIdx.x * blockDim.x + threadIdx.x;
    if (i >= n4) return;
    float4 v = ((const float4*)a)[i];
    half h0 = __float2half_rn(v.x), h1 = __float2half_rn(v.y);
    half h2 = __float2half_rn(v.z), h3 = __float2half_rn(v.w);
    half l0 = __float2half_rn(v.x - __half2float(h0));
    half l1 = __float2half_rn(v.y - __half2float(h1));
    half l2 = __float2half_rn(v.z - __half2float(h2));
    half l3 = __float2half_rn(v.w - __half2float(h3));
    uint2 hv, lv;
    hv.x = ((uint32_t)__half_as_ushort(h1) << 16) | __half_as_ushort(h0);
    hv.y = ((uint32_t)__half_as_ushort(h3) << 16) | __half_as_ushort(h2);
    lv.x = ((uint32_t)__half_as_ushort(l1) << 16) | __half_as_ushort(l0);
    lv.y = ((uint32_t)__half_as_ushort(l3) << 16) | __half_as_ushort(l2);
    ((uint2*)hi)[i] = hv;
    ((uint2*)lo)[i] = lv;
}

// transpose + fp16 split of both W1 and W2 live matrices in ONE launch.
__global__ void wconv12_kernel(const float* __restrict__ W1, const float* __restrict__ W2,
                               half* __restrict__ W1hi, half* __restrict__ W1lo,
                               half* __restrict__ W2hi, half* __restrict__ W2lo)
{
    __shared__ float t[32][33];
    const int z = blockIdx.z;
    const int isW2 = z >= 6;
    const int m = c_WMAP[isW2 ? z - 6 : z];
    const float* W = (isW2 ? W2 : W1) + (size_t)m * HID * HID;
    half* Whi = (isW2 ? W2hi : W1hi);
    half* Wlo = (isW2 ? W2lo : W1lo);
    const int k0 = blockIdx.x * 32, n0 = blockIdx.y * 32;
    const int tx = threadIdx.x, ty = threadIdx.y;
#pragma unroll
    for (int i = 0; i < 4; i++)
        t[ty + i * 8][tx] = W[(size_t)(k0 + ty + i * 8) * HID + n0 + tx];
    __syncthreads();
    const size_t ob = (size_t)m * HID * HID;
#pragma unroll
    for (int i = 0; i < 4; i++) {
        int n = n0 + ty + i * 8, k = k0 + tx;
        float v = t[tx][ty + i * 8];
        half h = __float2half_rn(v);
        Whi[ob + (size_t)n * HID + k] = h;
        Wlo[ob + (size_t)n * HID + k] = __float2half_rn(v - __half2float(h));
    }
}

// transpose + fp16 split: W_in[m][Kd][Nd] fp32 -> Wt[m][Nd][Kd] hi/lo
__global__ void wconv_kernel(const float* __restrict__ W,
                             half* __restrict__ Whi, half* __restrict__ Wlo,
                             int Kd, int Nd)
{
    __shared__ float t[32][33];
    const int m = blockIdx.z;
    const int k0 = blockIdx.x * 32, n0 = blockIdx.y * 32;
    const int tx = threadIdx.x, ty = threadIdx.y;
    const float* Wm = W + (size_t)m * Kd * Nd;
#pragma unroll
    for (int i = 0; i < 4; i++)
        t[ty + i * 8][tx] = Wm[(size_t)(k0 + ty + i * 8) * Nd + n0 + tx];
    __syncthreads();
    const size_t ob = (size_t)m * Kd * Nd;
#pragma unroll
    for (int i = 0; i < 4; i++) {
        int n = n0 + ty + i * 8, k = k0 + tx;
        float v = t[tx][ty + i * 8];
        half h = __float2half_rn(v);
        Whi[ob + (size_t)n * Kd + k] = h;
        Wlo[ob + (size_t)n * Kd + k] = __float2half_rn(v - __half2float(h));
    }
}

// ---------------------------------------------------------------------
// Fused final: out[i] = dot(relu(y1[i]+y4[i]), Wout) + bout  (one warp/row)
// ---------------------------------------------------------------------
__global__ void head2_kernel(const float* __restrict__ y1, const float* __restrict__ y4,
                             const float* __restrict__ Wout, const float* __restrict__ bout,
                             float* __restrict__ out, int M)
{
    const int gw = (int)((blockIdx.x * (size_t)blockDim.x + threadIdx.x) >> 5);
    const int lane = threadIdx.x & 31;
    if (gw >= M) return;
    const float* r1 = y1 + (size_t)gw * HID;
    const float* r4 = y4 + (size_t)gw * HID;
    float s = 0.f;
#pragma unroll
    for (int i = 0; i < 4; i++) {
        int c = (lane + i * 32) * 4;
        float4 a = *(const float4*)(r1 + c);
        float4 b = *(const float4*)(r4 + c);
        float4 w = *(const float4*)(Wout + c);
        s += fmaxf(a.x + b.x, 0.f) * w.x + fmaxf(a.y + b.y, 0.f) * w.y
           + fmaxf(a.z + b.z, 0.f) * w.z + fmaxf(a.w + b.w, 0.f) * w.w;
    }
#pragma unroll
    for (int o = 16; o; o >>= 1) s += __shfl_xor_sync(0xffffffffu, s, o);
    if (lane == 0) out[gw] = s + bout[0];
}

// ---------------------------------------------------------------------
extern "C" void kernel_launch(void* const* d_in, const int* in_sizes, int n_in,
                              void* d_out, int out_size)
{
    const float* x_all = (const float*)d_in[0];
    const float* W_in  = (const float*)d_in[1];
    const float* b_in  = (const float*)d_in[2];
    const float* W1    = (const float*)d_in[3];
    const float* b1    = (const float*)d_in[4];
    const float* W2    = (const float*)d_in[5];
    const float* b2    = (const float*)d_in[6];
    const float* W_out = (const float*)d_in[7];
    const float* b_out = (const float*)d_in[8];
    const int*   edges = (const int*)d_in[9];
    float* out = (float*)d_out;

    float *h, *h2, *y1, *y4;
    int *cnt, *off, *curp, *eidx;
    half *Ahi, *Alo, *Mhi, *Mlo, *xhi, *xlo, *Winhi, *Winlo, *W1hi, *W1lo, *W2hi, *W2lo;
    cudaGetSymbolAddress((void**)&h,    g_h);
    cudaGetSymbolAddress((void**)&h2,   g_h2);
    cudaGetSymbolAddress((void**)&y1,   g_y1);
    cudaGetSymbolAddress((void**)&y4,   g_y4);
    cudaGetSymbolAddress((void**)&cnt,  g_cnt);
    cudaGetSymbolAddress((void**)&off,  g_off);
    cudaGetSymbolAddress((void**)&curp, g_curp);
    cudaGetSymbolAddress((void**)&eidx, g_eidx);
    cudaGetSymbolAddress((void**)&Ahi,  g_Ahi);
    cudaGetSymbolAddress((void**)&Alo,  g_Alo);
    cudaGetSymbolAddress((void**)&Mhi,  g_Mhi);
    cudaGetSymbolAddress((void**)&Mlo,  g_Mlo);
    cudaGetSymbolAddress((void**)&xhi,  g_xhi);
    cudaGetSymbolAddress((void**)&xlo,  g_xlo);
    cudaGetSymbolAddress((void**)&Winhi, g_Winhi);
    cudaGetSymbolAddress((void**)&Winlo, g_Winlo);
    cudaGetSymbolAddress((void**)&W1hi, g_W1hi);
    cudaGetSymbolAddress((void**)&W1lo, g_W1lo);
    cudaGetSymbolAddress((void**)&W2hi, g_W2hi);
    cudaGetSymbolAddress((void**)&W2lo, g_W2lo);

    cudaFuncSetAttribute(gemm_mma_b<0,512>, cudaFuncAttributeMaxDynamicSharedMemorySize, MS_TOTAL);
    cudaFuncSetAttribute(gemm_mma_b<1,512>, cudaFuncAttributeMaxDynamicSharedMemorySize, MS_TOTAL);
    cudaFuncSetAttribute(gemm_mma_b<2,64>,  cudaFuncAttributeMaxDynamicSharedMemorySize, MS_TOTAL);

    const size_t WOFF = (size_t)HID * HID;
    const int gx = (NNODES + 127) / 128;

    // ---- weight prep + input split first (inproj's only dependencies) ----
    wconv12_kernel<<<dim3(16, 16, 12), dim3(32, 8)>>>(W1, W2, W1hi, W1lo, W2hi, W2lo);
    wconv_kernel<<<dim3(2, 16, NTYPES), dim3(32, 8)>>>(W_in, Winhi, Winlo, FIN, HID);
    {
        const int xn4 = NTYPES * NNODES * FIN / 4;
        split_kernel<<<(xn4 + 255) / 256, 256>>>(x_all, xhi, xlo, xn4);
    }

    // ---- input projection: all 5 types in one batched launch ----
    gemm_mma_b<2,64><<<dim3(gx, 4, NTYPES), 256, MS_TOTAL>>>(
        xhi, xlo, (size_t)NNODES * FIN, TL_ID, Winhi, Winlo, b_in,
        h, nullptr, nullptr, nullptr, nullptr, NNODES);

    // ---- CSR build (active edge types only) — needed only by the gather,
    //      so it rides behind the inproj GEMM in stream order ----
    cudaMemsetAsync(cnt, 0, (size_t)NET * NNODES * sizeof(int));
    hist_kernel<<<(4 * NEDGE + 255) / 256, 256>>>(edges, cnt);
    scan_kernel<<<4, 1024>>>(cnt, off, curp);
    fill_kernel<<<(4 * NEDGE + 255) / 256, 256>>>(edges, curp, eidx);

    // ================= layer 0: active t = {0,1,3,4} =================
    gather_split_kernel<<<dim3(NNODES, 4), 128>>>(h, TL_L0, 0, nullptr, nullptr,
                                                  off, eidx, Ahi, Alo);
    gemm_mma_b<0,512><<<dim3(gx, 4, 4), 256, MS_TOTAL>>>(
        Ahi, Alo, TOFF, TL_L0, W1hi, W1lo, b1,
        nullptr, Mhi, Mlo, nullptr, nullptr, NNODES);
    // GEMM2-L0: t=0 -> relu -> h2[1]; t=3 -> relu -> h2[3]; t=1 -> y1; t=4 -> y4
    gemm_mma_b<1,512><<<dim3(gx, 4, 4), 256, MS_TOTAL>>>(
        Mhi, Mlo, TOFF, TL_L0, W2hi, W2lo, b2,
        h2, nullptr, nullptr, y1, y4, NNODES);

    // ================= layer 1: active t = {1,4}; dst-0 self term from y1+y4 ====
    gather_split_kernel<<<dim3(NNODES, 2), 128>>>(h2, TL_L1, 1, y1, y4,
                                                  off, eidx, Ahi, Alo);
    gemm_mma_b<0,512><<<dim3(gx, 4, 2), 256, MS_TOTAL>>>(
        Ahi, Alo, TOFF, TL_L1, W1hi + (size_t)NET * WOFF, W1lo + (size_t)NET * WOFF,
        b1 + (size_t)NET * HID, nullptr, Mhi, Mlo, nullptr, nullptr, NNODES);
    gemm_mma_b<1,512><<<dim3(gx, 4, 2), 256, MS_TOTAL>>>(
        Mhi, Mlo, TOFF, TL_L1, W2hi + (size_t)NET * WOFF, W2lo + (size_t)NET * WOFF,
        b2 + (size_t)NET * HID, nullptr, nullptr, nullptr, y1, y4, NNODES);

    // ---- fused combine + output head on 'product' nodes ----
    head2_kernel<<<(NNODES * 32 + 255) / 256, 256>>>(y1, y4, W_out, b_out, out, NNODES);
}

// round 17
// speedup vs baseline: 1.0136x; 1.0136x over previous
#include <cuda_runtime.h>
#include <cuda_bf16.h>
#include <cstdint>
#include <cstddef>

#define NNODES 20000
#define HID    512
#define NEDGE  160000
#define NTYPES 5
#define NET    6
#define FIN    64
#define NWMAT  12
#define TOFF   ((size_t)NNODES * HID)

// ---------------- scratch (__device__ globals; no allocs allowed) -------------
__device__ float g_h  [NTYPES * NNODES * HID];
__device__ float g_h2 [NTYPES * NNODES * HID];
__device__ float g_y1 [NNODES * HID];
__device__ float g_y4 [NNODES * HID];
__device__ __nv_bfloat16 g_Ahi[NET * NNODES * HID];
__device__ __nv_bfloat16 g_Alo[NET * NNODES * HID];
__device__ __nv_bfloat16 g_Mhi[NET * NNODES * HID];
__device__ __nv_bfloat16 g_Mlo[NET * NNODES * HID];
__device__ __nv_bfloat16 g_xhi[NTYPES * NNODES * FIN];
__device__ __nv_bfloat16 g_xlo[NTYPES * NNODES * FIN];
__device__ __nv_bfloat16 g_Winhi[NTYPES * HID * FIN];
__device__ __nv_bfloat16 g_Winlo[NTYPES * HID * FIN];
__device__ __nv_bfloat16 g_W1hi[NWMAT * HID * HID];
__device__ __nv_bfloat16 g_W1lo[NWMAT * HID * HID];
__device__ __nv_bfloat16 g_W2hi[NWMAT * HID * HID];
__device__ __nv_bfloat16 g_W2lo[NWMAT * HID * HID];
// CSR scratch
__device__ int g_cnt [NET * NNODES];
__device__ int g_off [NET * (NNODES + 1)];
__device__ int g_curp[NET * NNODES];
__device__ int g_eidx[NET * NEDGE];

// EDGE_TYPES = ((4,1),(1,0),(0,2),(2,3),(3,0),(1,4))
__constant__ int c_ES[NET] = {4, 1, 0, 2, 3, 1};
__constant__ int c_ED[NET] = {1, 0, 2, 3, 0, 4};
// Dead-cone-pruned active type lists:
//  [0..5] identity; [6..9] layer 0: {0,1,3,4}; [10..11] layer 1: {1,4}
__constant__ int c_TLA[12] = {0, 1, 2, 3, 4, 5,  0, 1, 3, 4,  1, 4};
#define TL_ID 0
#define TL_L0 6
#define TL_L1 10
__constant__ int c_WMAP[6] = {0, 1, 3, 4, 7, 10};   // live (l*NET+t) weight mats
__constant__ int c_CSRT[4] = {0, 1, 3, 4};          // edge types ever gathered

// ---------------- family-common PTX helpers (sm_80+) --------------------------
__device__ __forceinline__ uint32_t smem_u32(const void* p) {
    uint32_t a;
    asm("{ .reg .u64 t; cvta.to.shared.u64 t, %1; cvt.u32.u64 %0, t; }" : "=r"(a) : "l"(p));
    return a;
}
__device__ __forceinline__ void cpasync16(uint32_t s, const void* g, int sz) {
    asm volatile("cp.async.cg.shared.global [%0], [%1], 16, %2;" :: "r"(s), "l"(g), "r"(sz));
}
__device__ __forceinline__ void cp_commit() { asm volatile("cp.async.commit_group;"); }
template<int N>
__device__ __forceinline__ void cp_wait() { asm volatile("cp.async.wait_group %0;" :: "n"(N)); }

__device__ __forceinline__ void ldsm4(uint32_t* r, uint32_t a) {
    asm volatile("ldmatrix.sync.aligned.m8n8.x4.shared.b16 {%0,%1,%2,%3}, [%4];"
                 : "=r"(r[0]), "=r"(r[1]), "=r"(r[2]), "=r"(r[3]) : "r"(a));
}
__device__ __forceinline__ void ldsm2(uint32_t* r, uint32_t a) {
    asm volatile("ldmatrix.sync.aligned.m8n8.x2.shared.b16 {%0,%1}, [%2];"
                 : "=r"(r[0]), "=r"(r[1]) : "r"(a));
}
__device__ __forceinline__ void mma16816(float* d, const uint32_t* a, const uint32_t* b) {
    asm volatile("mma.sync.aligned.m16n8k16.row.col.f32.bf16.bf16.f32 "
                 "{%0,%1,%2,%3}, {%4,%5,%6,%7}, {%8,%9}, {%0,%1,%2,%3};"
                 : "+f"(d[0]), "+f"(d[1]), "+f"(d[2]), "+f"(d[3])
                 : "r"(a[0]), "r"(a[1]), "r"(a[2]), "r"(a[3]), "r"(b[0]), "r"(b[1]));
}
__device__ __forceinline__ void bf16_split2(float v0, float v1, uint32_t& hp, uint32_t& lp) {
    __nv_bfloat16 h0 = __float2bfloat16(v0), h1 = __float2bfloat16(v1);
    float l0 = v0 - __bfloat162float(h0);
    float l1 = v1 - __bfloat162float(h1);
    __nv_bfloat16 q0 = __float2bfloat16(l0), q1 = __float2bfloat16(l1);
    hp = ((uint32_t)__bfloat16_as_ushort(h1) << 16) | __bfloat16_as_ushort(h0);
    lp = ((uint32_t)__bfloat16_as_ushort(q1) << 16) | __bfloat16_as_ushort(q0);
}

// ---------------------------------------------------------------------
// Batched 3-product split-bf16 GEMM on mma.sync; t = c_TLA[tlbase + blockIdx.z].
// 2-stage cp.async pipeline + OCCUPANCY 2 (smem 80KB/CTA, regs capped 128):
// the co-resident CTA fills sync/epilogue latency (R15-measured: -240us).
// MODE 0: GEMM1  -> relu, bf16 hi/lo out to Chi/Clo + t*TOFF
// MODE 1: GEMM2  -> t==1 raw->y1, t==4 raw->y4, else relu -> C + ED[t]*TOFF
// MODE 2: inproj -> relu -> fp32 C + t*TOFF
// CTA 128x128, BK=32, 8 warps; Ahi*Bhi + Ahi*Blo + Alo*Bhi, fp32 acc.
// ---------------------------------------------------------------------
#define MS_A_HI 0
#define MS_A_LO 10240
#define MS_B_HI 20480
#define MS_B_LO 30720
#define MS_STAGE 40960
#define MS_TOTAL (2 * MS_STAGE)

template<int MODE, int LDK>
__global__ __launch_bounds__(256, 2)
void gemm_mma_b(const __nv_bfloat16* __restrict__ Ahi, const __nv_bfloat16* __restrict__ Alo,
                size_t aStride, int tlbase,
                const __nv_bfloat16* __restrict__ Whi, const __nv_bfloat16* __restrict__ Wlo,
                const float* __restrict__ bias,
                float* __restrict__ C,
                __nv_bfloat16* __restrict__ Chi, __nv_bfloat16* __restrict__ Clo,
                float* __restrict__ y1, float* __restrict__ y4,
                int M)
{
    constexpr int NKT = LDK / 32;
    extern __shared__ char smem[];
    const uint32_t sb = smem_u32(smem);
    const int t    = c_TLA[tlbase + blockIdx.z];
    const int tid  = threadIdx.x;
    const int lane = tid & 31;
    const int wid  = tid >> 5;
    const int wm   = (wid >> 2) * 64;
    const int wn   = (wid & 3) * 32;
    const int bm   = blockIdx.x * 128;
    const int bn   = blockIdx.y * 128;

    Ahi += (size_t)t * aStride;
    Alo += (size_t)t * aStride;
    Whi += (size_t)t * (size_t)HID * LDK;
    Wlo += (size_t)t * (size_t)HID * LDK;
    bias += (size_t)t * HID;

    auto load_stage = [&](int st, int kt) {
        const int kc = kt * 32;
        const uint32_t sbase = sb + st * MS_STAGE;
#pragma unroll
        for (int j = 0; j < 2; ++j) {
            const int c   = tid + j * 256;
            const int row = c >> 2;
            const int c16 = c & 3;
            const uint32_t so = (uint32_t)(row * 80 + c16 * 16);
            const int gr = bm + row;
            const int sz = (gr < M) ? 16 : 0;
            const size_t ga = (size_t)gr * LDK + kc + c16 * 8;
            cpasync16(sbase + MS_A_HI + so, Ahi + ga, sz);
            cpasync16(sbase + MS_A_LO + so, Alo + ga, sz);
            const size_t gb = (size_t)(bn + row) * LDK + kc + c16 * 8;
            cpasync16(sbase + MS_B_HI + so, Whi + gb, 16);
            cpasync16(sbase + MS_B_LO + so, Wlo + gb, 16);
        }
        cp_commit();
    };

    float acc[4][4][4];
#pragma unroll
    for (int mi = 0; mi < 4; ++mi)
#pragma unroll
        for (int ni = 0; ni < 4; ++ni)
#pragma unroll
            for (int q = 0; q < 4; ++q) acc[mi][ni][q] = 0.f;

    load_stage(0, 0);

    const uint32_t a_row = (uint32_t)(lane & 15);
    const uint32_t a_k16 = (uint32_t)((lane >> 4) * 16);
    const uint32_t b_row = (uint32_t)(lane & 7);
    const uint32_t b_k16 = (uint32_t)(((lane >> 3) & 1) * 16);

#pragma unroll 1
    for (int kt = 0; kt < NKT; ++kt) {
        if (kt + 1 < NKT) { load_stage((kt + 1) & 1, kt + 1); cp_wait<1>(); }
        else              { cp_wait<0>(); }
        __syncthreads();

        const uint32_t sbase = sb + (uint32_t)(kt & 1) * MS_STAGE;
#pragma unroll
        for (int k2 = 0; k2 < 2; ++k2) {
            const uint32_t koff = (uint32_t)(k2 * 32);
            uint32_t ah[4][4], al[4][4], bh[4][2], bl[4][2];
#pragma unroll
            for (int mi = 0; mi < 4; ++mi) {
                uint32_t ad = sbase + (uint32_t)((wm + mi * 16 + a_row) * 80) + a_k16 + koff;
                ldsm4(ah[mi], ad + MS_A_HI);
                ldsm4(al[mi], ad + MS_A_LO);
            }
#pragma unroll
            for (int ni = 0; ni < 4; ++ni) {
                uint32_t bd = sbase + (uint32_t)((wn + ni * 8 + b_row) * 80) + b_k16 + koff;
                ldsm2(bh[ni], bd + MS_B_HI);
                ldsm2(bl[ni], bd + MS_B_LO);
            }
#pragma unroll
            for (int mi = 0; mi < 4; ++mi)
#pragma unroll
                for (int ni = 0; ni < 4; ++ni) {
                    mma16816(acc[mi][ni], ah[mi], bh[ni]);
                    mma16816(acc[mi][ni], ah[mi], bl[ni]);
                    mma16816(acc[mi][ni], al[mi], bh[ni]);
                }
        }
        __syncthreads();   // stage (kt&1) must drain before the kt+1 iter reloads it
    }

    // ---- per-mode output routing ----
    float* Cout = nullptr;
    bool doRelu = true;
    if (MODE == 0) {
        Chi += (size_t)t * TOFF;
        Clo += (size_t)t * TOFF;
    } else if (MODE == 1) {
        const int d = c_ED[t];
        if (t == 1)      { Cout = y1; doRelu = false; }
        else if (t == 4) { Cout = y4; doRelu = false; }
        else             { Cout = C + (size_t)d * TOFF; }
    } else {
        Cout = C + (size_t)t * TOFF;
    }

#pragma unroll
    for (int mi = 0; mi < 4; ++mi) {
        const int r0 = bm + wm + mi * 16 + (lane >> 2);
#pragma unroll
        for (int half = 0; half < 2; ++half) {
            const int r = r0 + half * 8;
            if (r >= M) continue;
#pragma unroll
            for (int ni = 0; ni < 4; ++ni) {
                const int c = wn + ni * 8 + (lane & 3) * 2 + bn;
                float v0 = acc[mi][ni][half * 2 + 0] + bias[c];
                float v1 = acc[mi][ni][half * 2 + 1] + bias[c + 1];
                if (MODE == 0) {
                    v0 = fmaxf(v0, 0.f); v1 = fmaxf(v1, 0.f);
                    uint32_t hp, lp;
                    bf16_split2(v0, v1, hp, lp);
                    *(uint32_t*)(Chi + (size_t)r * HID + c) = hp;
                    *(uint32_t*)(Clo + (size_t)r * HID + c) = lp;
                } else {
                    if (doRelu) { v0 = fmaxf(v0, 0.f); v1 = fmaxf(v1, 0.f); }
                    *(float2*)(Cout + (size_t)r * HID + c) = make_float2(v0, v1);
                }
            }
        }
    }
}

// ---------------------------------------------------------------------
// CSR build for ACTIVE edge types only: histogram -> scan -> fill
// ---------------------------------------------------------------------
__global__ void hist_kernel(const int* __restrict__ edges, int* __restrict__ cnt)
{
    const int i = blockIdx.x * blockDim.x + threadIdx.x;
    if (i >= 4 * NEDGE) return;
    const int t = c_CSRT[i / NEDGE], e = i % NEDGE;
    const int d = edges[(size_t)t * 2 * NEDGE + NEDGE + e];
    atomicAdd(&cnt[t * NNODES + d], 1);
}

__global__ void scan_kernel(const int* __restrict__ cnt, int* __restrict__ off,
                            int* __restrict__ curp)
{
    const int t = c_CSRT[blockIdx.x];
    const int tid = threadIdx.x;
    const int lane = tid & 31, wid = tid >> 5;
    __shared__ int wsum[32];
    __shared__ int chunkTotal;
    int carry = 0;
    for (int base = 0; base < NNODES; base += 1024) {
        const int idx = base + tid;
        int v = (idx < NNODES) ? cnt[t * NNODES + idx] : 0;
        int x = v;
#pragma unroll
        for (int o = 1; o < 32; o <<= 1) {
            int y = __shfl_up_sync(0xffffffffu, x, o);
            if (lane >= o) x += y;
        }
        if (lane == 31) wsum[wid] = x;
        __syncthreads();
        if (wid == 0) {
            int w = wsum[lane];
#pragma unroll
            for (int o = 1; o < 32; o <<= 1) {
                int y = __shfl_up_sync(0xffffffffu, w, o);
                if (lane >= o) w += y;
            }
            wsum[lane] = w;
            if (lane == 31) chunkTotal = w;
        }
        __syncthreads();
        const int incl = x + (wid > 0 ? wsum[wid - 1] : 0);
        const int excl = carry + incl - v;
        if (idx < NNODES) {
            off[t * (NNODES + 1) + idx] = excl;
            curp[t * NNODES + idx] = excl;
        }
        carry += chunkTotal;
        __syncthreads();
    }
    if (tid == 0) off[t * (NNODES + 1) + NNODES] = carry;
}

__global__ void fill_kernel(const int* __restrict__ edges, int* __restrict__ curp,
                            int* __restrict__ eidx)
{
    const int i = blockIdx.x * blockDim.x + threadIdx.x;
    if (i >= 4 * NEDGE) return;
    const int t = c_CSRT[i / NEDGE], e = i % NEDGE;
    const int s = edges[(size_t)t * 2 * NEDGE + e];
    const int d = edges[(size_t)t * 2 * NEDGE + NEDGE + e];
    const int p = atomicAdd(&curp[t * NNODES + d], 1);
    eidx[t * NEDGE + p] = s;
}

// ---------------------------------------------------------------------
// Fused GIN aggregation via CSR gather + bf16 hi/lo split (proven 128-thr form;
// L2-bandwidth-bound at its floor).
// Layer 1 (useY): dst-0 self term computed inline as relu(y1[d] + y4[d]).
// ---------------------------------------------------------------------
__global__ __launch_bounds__(128)
void gather_split_kernel(const float* __restrict__ hcur, int tlbase, int useY,
                         const float* __restrict__ y1, const float* __restrict__ y4,
                         const int* __restrict__ off, const int* __restrict__ eidx,
                         __nv_bfloat16* __restrict__ Ahi, __nv_bfloat16* __restrict__ Alo)
{
    const int d = blockIdx.x;
    const int t = c_TLA[tlbase + blockIdx.y];
    const int c4 = threadIdx.x * 4;
    const int o0 = off[t * (NNODES + 1) + d];
    const int o1 = off[t * (NNODES + 1) + d + 1];
    const float* hsrc = hcur + (size_t)c_ES[t] * TOFF;
    const int* ei = eidx + (size_t)t * NEDGE;

    float4 acc;
    if (useY) {
        const float4 a = *(const float4*)(y1 + (size_t)d * HID + c4);
        const float4 b = *(const float4*)(y4 + (size_t)d * HID + c4);
        acc.x = fmaxf(a.x + b.x, 0.f);
        acc.y = fmaxf(a.y + b.y, 0.f);
        acc.z = fmaxf(a.z + b.z, 0.f);
        acc.w = fmaxf(a.w + b.w, 0.f);
    } else {
        acc = *(const float4*)(hcur + (size_t)c_ED[t] * TOFF + (size_t)d * HID + c4);
    }
#pragma unroll 4
    for (int e = o0; e < o1; ++e) {
        const int s = __ldg(&ei[e]);
        const float4 v = *(const float4*)(hsrc + (size_t)s * HID + c4);
        acc.x += v.x; acc.y += v.y; acc.z += v.z; acc.w += v.w;
    }
    uint2 hv, lv;
    bf16_split2(acc.x, acc.y, hv.x, lv.x);
    bf16_split2(acc.z, acc.w, hv.y, lv.y);
    *(uint2*)(Ahi + (size_t)t * TOFF + (size_t)d * HID + c4) = hv;
    *(uint2*)(Alo + (size_t)t * TOFF + (size_t)d * HID + c4) = lv;
}

// ---------------------------------------------------------------------
__global__ void split_kernel(const float* __restrict__ a,
                             __nv_bfloat16* __restrict__ hi, __nv_bfloat16* __restrict__ lo,
                             int n4)
{
    int i = blockIdx.x * blockDim.x + threadIdx.x;
    if (i >= n4) return;
    float4 v = ((const float4*)a)[i];
    uint2 hv, lv;
    bf16_split2(v.x, v.y, hv.x, lv.x);
    bf16_split2(v.z, v.w, hv.y, lv.y);
    ((uint2*)hi)[i] = hv;
    ((uint2*)lo)[i] = lv;
}

// transpose + bf16 split of both W1 and W2 live matrices in ONE launch.
__global__ void wconv12_kernel(const float* __restrict__ W1, const float* __restrict__ W2,
                               __nv_bfloat16* __restrict__ W1hi, __nv_bfloat16* __restrict__ W1lo,
                               __nv_bfloat16* __restrict__ W2hi, __nv_bfloat16* __restrict__ W2lo)
{
    __shared__ float t[32][33];
    const int z = blockIdx.z;
    const int isW2 = z >= 6;
    const int m = c_WMAP[isW2 ? z - 6 : z];
    const float* W = (isW2 ? W2 : W1) + (size_t)m * HID * HID;
    __nv_bfloat16* Whi = (isW2 ? W2hi : W1hi);
    __nv_bfloat16* Wlo = (isW2 ? W2lo : W1lo);
    const int k0 = blockIdx.x * 32, n0 = blockIdx.y * 32;
    const int tx = threadIdx.x, ty = threadIdx.y;
#pragma unroll
    for (int i = 0; i < 4; i++)
        t[ty + i * 8][tx] = W[(size_t)(k0 + ty + i * 8) * HID + n0 + tx];
    __syncthreads();
    const size_t ob = (size_t)m * HID * HID;
#pragma unroll
    for (int i = 0; i < 4; i++) {
        int n = n0 + ty + i * 8, k = k0 + tx;
        float v = t[tx][ty + i * 8];
        __nv_bfloat16 h = __float2bfloat16(v);
        Whi[ob + (size_t)n * HID + k] = h;
        Wlo[ob + (size_t)n * HID + k] = __float2bfloat16(v - __bfloat162float(h));
    }
}

// transpose + bf16 split: W_in[m][Kd][Nd] fp32 -> Wt[m][Nd][Kd] hi/lo
__global__ void wconv_kernel(const float* __restrict__ W,
                             __nv_bfloat16* __restrict__ Whi, __nv_bfloat16* __restrict__ Wlo,
                             int Kd, int Nd)
{
    __shared__ float t[32][33];
    const int m = blockIdx.z;
    const int k0 = blockIdx.x * 32, n0 = blockIdx.y * 32;
    const int tx = threadIdx.x, ty = threadIdx.y;
    const float* Wm = W + (size_t)m * Kd * Nd;
#pragma unroll
    for (int i = 0; i < 4; i++)
        t[ty + i * 8][tx] = Wm[(size_t)(k0 + ty + i * 8) * Nd + n0 + tx];
    __syncthreads();
    const size_t ob = (size_t)m * Kd * Nd;
#pragma unroll
    for (int i = 0; i < 4; i++) {
        int n = n0 + ty + i * 8, k = k0 + tx;
        float v = t[tx][ty + i * 8];
        __nv_bfloat16 h = __float2bfloat16(v);
        Whi[ob + (size_t)n * Kd + k] = h;
        Wlo[ob + (size_t)n * Kd + k] = __float2bfloat16(v - __bfloat162float(h));
    }
}

// ---------------------------------------------------------------------
// Fused final: out[i] = dot(relu(y1[i]+y4[i]), Wout) + bout  (one warp/row)
// ---------------------------------------------------------------------
__global__ void head2_kernel(const float* __restrict__ y1, const float* __restrict__ y4,
                             const float* __restrict__ Wout, const float* __restrict__ bout,
                             float* __restrict__ out, int M)
{
    const int gw = (int)((blockIdx.x * (size_t)blockDim.x + threadIdx.x) >> 5);
    const int lane = threadIdx.x & 31;
    if (gw >= M) return;
    const float* r1 = y1 + (size_t)gw * HID;
    const float* r4 = y4 + (size_t)gw * HID;
    float s = 0.f;
#pragma unroll
    for (int i = 0; i < 4; i++) {
        int c = (lane + i * 32) * 4;
        float4 a = *(const float4*)(r1 + c);
        float4 b = *(const float4*)(r4 + c);
        float4 w = *(const float4*)(Wout + c);
        s += fmaxf(a.x + b.x, 0.f) * w.x + fmaxf(a.y + b.y, 0.f) * w.y
           + fmaxf(a.z + b.z, 0.f) * w.z + fmaxf(a.w + b.w, 0.f) * w.w;
    }
#pragma unroll
    for (int o = 16; o; o >>= 1) s += __shfl_xor_sync(0xffffffffu, s, o);
    if (lane == 0) out[gw] = s + bout[0];
}

// ---------------------------------------------------------------------
extern "C" void kernel_launch(void* const* d_in, const int* in_sizes, int n_in,
                              void* d_out, int out_size)
{
    const float* x_all = (const float*)d_in[0];
    const float* W_in  = (const float*)d_in[1];
    const float* b_in  = (const float*)d_in[2];
    const float* W1    = (const float*)d_in[3];
    const float* b1    = (const float*)d_in[4];
    const float* W2    = (const float*)d_in[5];
    const float* b2    = (const float*)d_in[6];
    const float* W_out = (const float*)d_in[7];
    const float* b_out = (const float*)d_in[8];
    const int*   edges = (const int*)d_in[9];
    float* out = (float*)d_out;

    float *h, *h2, *y1, *y4;
    int *cnt, *off, *curp, *eidx;
    __nv_bfloat16 *Ahi, *Alo, *Mhi, *Mlo, *xhi, *xlo, *Winhi, *Winlo, *W1hi, *W1lo, *W2hi, *W2lo;
    cudaGetSymbolAddress((void**)&h,    g_h);
    cudaGetSymbolAddress((void**)&h2,   g_h2);
    cudaGetSymbolAddress((void**)&y1,   g_y1);
    cudaGetSymbolAddress((void**)&y4,   g_y4);
    cudaGetSymbolAddress((void**)&cnt,  g_cnt);
    cudaGetSymbolAddress((void**)&off,  g_off);
    cudaGetSymbolAddress((void**)&curp, g_curp);
    cudaGetSymbolAddress((void**)&eidx, g_eidx);
    cudaGetSymbolAddress((void**)&Ahi,  g_Ahi);
    cudaGetSymbolAddress((void**)&Alo,  g_Alo);
    cudaGetSymbolAddress((void**)&Mhi,  g_Mhi);
    cudaGetSymbolAddress((void**)&Mlo,  g_Mlo);
    cudaGetSymbolAddress((void**)&xhi,  g_xhi);
    cudaGetSymbolAddress((void**)&xlo,  g_xlo);
    cudaGetSymbolAddress((void**)&Winhi, g_Winhi);
    cudaGetSymbolAddress((void**)&Winlo, g_Winlo);
    cudaGetSymbolAddress((void**)&W1hi, g_W1hi);
    cudaGetSymbolAddress((void**)&W1lo, g_W1lo);
    cudaGetSymbolAddress((void**)&W2hi, g_W2hi);
    cudaGetSymbolAddress((void**)&W2lo, g_W2lo);

    cudaFuncSetAttribute(gemm_mma_b<0,512>, cudaFuncAttributeMaxDynamicSharedMemorySize, MS_TOTAL);
    cudaFuncSetAttribute(gemm_mma_b<1,512>, cudaFuncAttributeMaxDynamicSharedMemorySize, MS_TOTAL);
    cudaFuncSetAttribute(gemm_mma_b<2,64>,  cudaFuncAttributeMaxDynamicSharedMemorySize, MS_TOTAL);

    const size_t WOFF = (size_t)HID * HID;
    const int gx = (NNODES + 127) / 128;

    // ---- CSR build (active edge types only) ----
    cudaMemsetAsync(cnt, 0, (size_t)NET * NNODES * sizeof(int));
    hist_kernel<<<(4 * NEDGE + 255) / 256, 256>>>(edges, cnt);
    scan_kernel<<<4, 1024>>>(cnt, off, curp);
    fill_kernel<<<(4 * NEDGE + 255) / 256, 256>>>(edges, curp, eidx);

    // ---- weight prep (live mats only, single launch for W1+W2) + input split ----
    wconv12_kernel<<<dim3(16, 16, 12), dim3(32, 8)>>>(W1, W2, W1hi, W1lo, W2hi, W2lo);
    wconv_kernel<<<dim3(2, 16, NTYPES), dim3(32, 8)>>>(W_in, Winhi, Winlo, FIN, HID);
    {
        const int xn4 = NTYPES * NNODES * FIN / 4;
        split_kernel<<<(xn4 + 255) / 256, 256>>>(x_all, xhi, xlo, xn4);
    }

    // ---- input projection: all 5 types in one batched launch ----
    gemm_mma_b<2,64><<<dim3(gx, 4, NTYPES), 256, MS_TOTAL>>>(
        xhi, xlo, (size_t)NNODES * FIN, TL_ID, Winhi, Winlo, b_in,
        h, nullptr, nullptr, nullptr, nullptr, NNODES);

    // ================= layer 0: active t = {0,1,3,4} =================
    gather_split_kernel<<<dim3(NNODES, 4), 128>>>(h, TL_L0, 0, nullptr, nullptr,
                                                  off, eidx, Ahi, Alo);
    gemm_mma_b<0,512><<<dim3(gx, 4, 4), 256, MS_TOTAL>>>(
        Ahi, Alo, TOFF, TL_L0, W1hi, W1lo, b1,
        nullptr, Mhi, Mlo, nullptr, nullptr, NNODES);
    // GEMM2-L0: t=0 -> relu -> h2[1]; t=3 -> relu -> h2[3]; t=1 -> y1; t=4 -> y4
    gemm_mma_b<1,512><<<dim3(gx, 4, 4), 256, MS_TOTAL>>>(
        Mhi, Mlo, TOFF, TL_L0, W2hi, W2lo, b2,
        h2, nullptr, nullptr, y1, y4, NNODES);

    // ================= layer 1: active t = {1,4}; dst-0 self term from y1+y4 ====
    gather_split_kernel<<<dim3(NNODES, 2), 128>>>(h2, TL_L1, 1, y1, y4,
                                                  off, eidx, Ahi, Alo);
    gemm_mma_b<0,512><<<dim3(gx, 4, 2), 256, MS_TOTAL>>>(
        Ahi, Alo, TOFF, TL_L1, W1hi + (size_t)NET * WOFF, W1lo + (size_t)NET * WOFF,
        b1 + (size_t)NET * HID, nullptr, Mhi, Mlo, nullptr, nullptr, NNODES);
    gemm_mma_b<1,512><<<dim3(gx, 4, 2), 256, MS_TOTAL>>>(
        Mhi, Mlo, TOFF, TL_L1, W2hi + (size_t)NET * WOFF, W2lo + (size_t)NET * WOFF,
        b2 + (size_t)NET * HID, nullptr, nullptr, nullptr, y1, y4, NNODES);

    // ---- fused combine + output head on 'product' nodes ----
    head2_kernel<<<(NNODES * 32 + 255) / 256, 256>>>(y1, y4, W_out, b_out, out, NNODES);
}